// round 5
// baseline (speedup 1.0000x reference)
#include <cuda_runtime.h>

// Problem constants
#define T_TOK 8192
#define K_CODE 8192
#define C_DIM 512

// EMA / loss constants (match reference's python-double -> f32 conversions)
#define DECAY_F 0.99f
#define OMD_F ((float)(1.0 - 0.99))     // == 0.01f bit pattern
#define EPS_F 1e-5f
#define KEPS_F 0.08192f                  // (float)(8192 * 1e-5)

// -------- scratch (device globals; no allocation allowed) --------
__device__ __align__(16) unsigned long long g_keys[T_TOK];
__device__ __align__(16) float g_stok[T_TOK];
__device__ __align__(16) float g_hcode[K_CODE];
__device__ __align__(16) float g_counts[K_CODE];
__device__ __align__(16) float g_embed_sum[(size_t)K_CODE * C_DIM];
__device__ double g_loss;
__device__ float g_nsum;

// ------------------------------------------------------------------
// K0: init scratch
// ------------------------------------------------------------------
__global__ void k_init() {
    size_t i = (size_t)blockIdx.x * blockDim.x + threadIdx.x;
    size_t stride = (size_t)gridDim.x * blockDim.x;
    float4 z4 = make_float4(0.f, 0.f, 0.f, 0.f);
    float4* es4 = (float4*)g_embed_sum;
    const size_t n4 = (size_t)K_CODE * C_DIM / 4;
    for (size_t j = i; j < n4; j += stride) es4[j] = z4;
    for (size_t j = i; j < K_CODE; j += stride) g_counts[j] = 0.f;
    for (size_t j = i; j < T_TOK; j += stride) g_keys[j] = ~0ull;
    if (i == 0) { g_loss = 0.0; g_nsum = 0.f; }
}

// ------------------------------------------------------------------
// K1: row norms  s[t] = sum z^2,  h[k] = sum e^2   (one warp per row)
// ------------------------------------------------------------------
__global__ void k_norms(const float* __restrict__ Z, const float* __restrict__ E) {
    int warp = (int)((blockIdx.x * blockDim.x + threadIdx.x) >> 5);
    int lane = threadIdx.x & 31;
    if (warp >= T_TOK + K_CODE) return;
    const float* p = (warp < T_TOK) ? (Z + (size_t)warp * C_DIM)
                                    : (E + (size_t)(warp - T_TOK) * C_DIM);
    const float4* p4 = (const float4*)p;
    float s = 0.f;
#pragma unroll
    for (int i = 0; i < C_DIM / 128; i++) {   // 4 float4 per lane
        float4 v = p4[lane + i * 32];
        s += v.x * v.x + v.y * v.y + v.z * v.z + v.w * v.w;
    }
#pragma unroll
    for (int off = 16; off; off >>= 1) s += __shfl_xor_sync(0xFFFFFFFFu, s, off);
    if (lane == 0) {
        if (warp < T_TOK) g_stok[warp] = s;
        else              g_hcode[warp - T_TOK] = s;
    }
}

// ------------------------------------------------------------------
// K2: fp32 GEMM (Z @ E^T) fused with argmin over codes.
//     128x128 block tile, BK=16, 8x8 per-thread microtile, 256 threads.
//     SMEM rows padded by +4 (132 floats = 528B = 33*16B) so every
//     &As[kk][8j] is 16B-aligned for LDS.128 (the +1 padding trapped).
//     dist = (s_t - 2*dot) + h_k  (same association as reference).
//     argmin via u64 key = (ordered_float(dist)<<32)|code, atomicMin
//     -> exact smallest-index tie-break, matching jnp.argmin.
// ------------------------------------------------------------------
#define BM 128
#define BN 128
#define BK 16
#define PAD 4

__device__ __forceinline__ unsigned f2ord(float f) {
    unsigned u = __float_as_uint(f);
    return (u & 0x80000000u) ? ~u : (u | 0x80000000u);
}

__global__ __launch_bounds__(256, 2) void k_gemm_argmin(
    const float* __restrict__ Z, const float* __restrict__ E)
{
    __shared__ __align__(16) float As[BK][BM + PAD];
    __shared__ __align__(16) float Bs[BK][BN + PAD];
    const int bm = blockIdx.y * BM;   // token base
    const int bn = blockIdx.x * BN;   // code base
    const int tid = threadIdx.x;
    const int tx = tid & 15;          // col group
    const int ty = tid >> 4;          // row group

    float acc[8][8];
#pragma unroll
    for (int i = 0; i < 8; i++)
#pragma unroll
        for (int j = 0; j < 8; j++) acc[i][j] = 0.f;

    const float* Zg = Z + (size_t)bm * C_DIM;
    const float* Eg = E + (size_t)bn * C_DIM;

    for (int k0 = 0; k0 < C_DIM; k0 += BK) {
        // load tiles (transposed into k-major smem), 2 float4 per thread per matrix
#pragma unroll
        for (int l = 0; l < 2; l++) {
            int c = tid + l * 256;          // 0..511
            int row = c >> 2;               // 0..127
            int kq = (c & 3) * 4;           // 0,4,8,12
            float4 v = *(const float4*)(Zg + (size_t)row * C_DIM + k0 + kq);
            As[kq + 0][row] = v.x; As[kq + 1][row] = v.y;
            As[kq + 2][row] = v.z; As[kq + 3][row] = v.w;
            float4 w = *(const float4*)(Eg + (size_t)row * C_DIM + k0 + kq);
            Bs[kq + 0][row] = w.x; Bs[kq + 1][row] = w.y;
            Bs[kq + 2][row] = w.z; Bs[kq + 3][row] = w.w;
        }
        __syncthreads();
#pragma unroll
        for (int kk = 0; kk < BK; kk++) {
            float a[8], b[8];
            *(float4*)&a[0] = *(const float4*)&As[kk][ty * 8];
            *(float4*)&a[4] = *(const float4*)&As[kk][ty * 8 + 4];
            *(float4*)&b[0] = *(const float4*)&Bs[kk][tx * 8];
            *(float4*)&b[4] = *(const float4*)&Bs[kk][tx * 8 + 4];
#pragma unroll
            for (int i = 0; i < 8; i++)
#pragma unroll
                for (int j = 0; j < 8; j++)
                    acc[i][j] = fmaf(a[i], b[j], acc[i][j]);
        }
        __syncthreads();
    }

    // epilogue: dist + per-row argmin over this 128-col tile
    float s[8];
#pragma unroll
    for (int i = 0; i < 8; i++) s[i] = g_stok[bm + ty * 8 + i];

    unsigned long long best[8];
#pragma unroll
    for (int i = 0; i < 8; i++) best[i] = ~0ull;

#pragma unroll
    for (int j = 0; j < 8; j++) {
        int code = bn + tx * 8 + j;
        float h = g_hcode[code];
#pragma unroll
        for (int i = 0; i < 8; i++) {
            float dist = (s[i] - 2.0f * acc[i][j]) + h;   // ref association
            unsigned long long key =
                ((unsigned long long)f2ord(dist) << 32) | (unsigned)code;
            best[i] = (key < best[i]) ? key : best[i];
        }
    }
    // reduce across the 16 lanes sharing the same rows (xor <=8 stays in half-warp)
#pragma unroll
    for (int off = 8; off; off >>= 1) {
#pragma unroll
        for (int i = 0; i < 8; i++) {
            unsigned long long o = __shfl_xor_sync(0xFFFFFFFFu, best[i], off);
            best[i] = (o < best[i]) ? o : best[i];
        }
    }
    if (tx == 0) {
#pragma unroll
        for (int i = 0; i < 8; i++)
            atomicMin(&g_keys[bm + ty * 8 + i], best[i]);
    }
}

// ------------------------------------------------------------------
// K3: per-token: gather z_q, straight-through out, loss, counts,
//     embed_sum scatter. One block (128 threads) per token.
// ------------------------------------------------------------------
__global__ void k_token(const float* __restrict__ Z, const float* __restrict__ E,
                        float* __restrict__ out_zq, float* __restrict__ out_idx)
{
    __shared__ float red[4];
    const int t = blockIdx.x;
    const int idx = (int)(g_keys[t] & 0xFFFFFFFFull);
    const float4* z4 = (const float4*)(Z + (size_t)t * C_DIM);
    const float4* e4 = (const float4*)(E + (size_t)idx * C_DIM);
    float4* o4 = (float4*)(out_zq + (size_t)t * C_DIM);
    float* es = g_embed_sum + (size_t)idx * C_DIM;

    const int i = threadIdx.x;   // 0..127 -> one float4 each (C/4 = 128)
    float4 zv = z4[i];
    float4 ev = e4[i];
    float4 o;
    o.x = zv.x + (ev.x - zv.x);  // straight-through, ref rounding order
    o.y = zv.y + (ev.y - zv.y);
    o.z = zv.z + (ev.z - zv.z);
    o.w = zv.w + (ev.w - zv.w);
    o4[i] = o;
    float dx = zv.x - ev.x, dy = zv.y - ev.y, dz = zv.z - ev.z, dw = zv.w - ev.w;
    float lsum = dx * dx + dy * dy + dz * dz + dw * dw;

    atomicAdd(&es[4 * i + 0], zv.x);
    atomicAdd(&es[4 * i + 1], zv.y);
    atomicAdd(&es[4 * i + 2], zv.z);
    atomicAdd(&es[4 * i + 3], zv.w);

#pragma unroll
    for (int off = 16; off; off >>= 1) lsum += __shfl_xor_sync(0xFFFFFFFFu, lsum, off);
    if ((i & 31) == 0) red[i >> 5] = lsum;
    __syncthreads();
    if (i == 0) {
        float tot = red[0] + red[1] + red[2] + red[3];
        out_idx[t] = (float)idx;
        atomicAdd(&g_counts[idx], 1.0f);
        atomicAdd(&g_loss, (double)tot);
    }
}

// ------------------------------------------------------------------
// K4: new_cluster_size + its global sum
// ------------------------------------------------------------------
__global__ void k_cluster(const float* __restrict__ cs, float* __restrict__ out_cs) {
    __shared__ float red[8];
    int k = blockIdx.x * 256 + threadIdx.x;
    float v = cs[k] * DECAY_F + g_counts[k] * OMD_F;
    out_cs[k] = v;
    float sum = v;
#pragma unroll
    for (int off = 16; off; off >>= 1) sum += __shfl_xor_sync(0xFFFFFFFFu, sum, off);
    if ((threadIdx.x & 31) == 0) red[threadIdx.x >> 5] = sum;
    __syncthreads();
    if (threadIdx.x == 0) {
        float tot = 0.f;
#pragma unroll
        for (int w = 0; w < 8; w++) tot += red[w];
        atomicAdd(&g_nsum, tot);
    }
}

// ------------------------------------------------------------------
// K5: new_embed_avg, new_codebook, vq_loss scalar.
//     NOTE: out_cb/out_ea offsets are 1 mod 4 floats -> scalar stores only.
// ------------------------------------------------------------------
__global__ void k_final(const float* __restrict__ ea, const float* __restrict__ ncs_arr,
                        float* __restrict__ out_cb, float* __restrict__ out_ea,
                        float* __restrict__ out_loss)
{
    const int k = blockIdx.x;
    if (k == 0 && threadIdx.x == 0) {
        out_loss[0] = 0.25f * (float)(g_loss / (double)((size_t)T_TOK * C_DIM));
    }
    float n = fmaxf(g_nsum, 1.0f);
    float ncs = ncs_arr[k];
    float sm = (ncs + EPS_F) / (n + KEPS_F) * n;

    const float4* a4 = (const float4*)(ea + (size_t)k * C_DIM);
    const float4* s4 = (const float4*)(g_embed_sum + (size_t)k * C_DIM);
    const int i = threadIdx.x;   // 0..127
    float4 av = a4[i];
    float4 sv = s4[i];
    float ne[4];
    ne[0] = av.x * DECAY_F + sv.x * OMD_F;
    ne[1] = av.y * DECAY_F + sv.y * OMD_F;
    ne[2] = av.z * DECAY_F + sv.z * OMD_F;
    ne[3] = av.w * DECAY_F + sv.w * OMD_F;
    size_t base = (size_t)k * C_DIM + 4 * i;
#pragma unroll
    for (int j = 0; j < 4; j++) {
        out_ea[base + j] = ne[j];
        out_cb[base + j] = ne[j] / sm;
    }
}

// ------------------------------------------------------------------
// launch
// ------------------------------------------------------------------
extern "C" void kernel_launch(void* const* d_in, const int* in_sizes, int n_in,
                              void* d_out, int out_size) {
    const float* Z  = (const float*)d_in[0];   // z_e        [8,1024,512]
    const float* E  = (const float*)d_in[1];   // codebook   [8192,512]
    const float* CS = (const float*)d_in[2];   // cluster_size [8192]
    const float* EA = (const float*)d_in[3];   // embed_avg  [8192,512]

    float* out = (float*)d_out;
    // concatenated outputs, reference return order:
    float* out_zq   = out;                                 // 4194304
    float* out_idx  = out_zq + (size_t)T_TOK * C_DIM;      // 8192
    float* out_loss = out_idx + T_TOK;                     // 1
    float* out_cb   = out_loss + 1;                        // 4194304
    float* out_cs   = out_cb + (size_t)K_CODE * C_DIM;     // 8192
    float* out_ea   = out_cs + K_CODE;                     // 4194304

    k_init<<<2048, 256>>>();
    k_norms<<<(T_TOK + K_CODE) / 8, 256>>>(Z, E);
    dim3 grid(K_CODE / BN, T_TOK / BM);
    k_gemm_argmin<<<grid, 256>>>(Z, E);
    k_token<<<T_TOK, 128>>>(Z, E, out_zq, out_idx);
    k_cluster<<<K_CODE / 256, 256>>>(CS, out_cs);
    k_final<<<K_CODE, 128>>>(EA, out_cs, out_cb, out_ea, out_loss);
}

// round 8
// speedup vs baseline: 1.4750x; 1.4750x over previous
#include <cuda_runtime.h>
#include <cuda_bf16.h>
#include <cstdint>

// Problem constants
#define T_TOK 8192
#define K_CODE 8192
#define C_DIM 512
#define KSPLIT 1536            // 3 * C_DIM (bf16 hi|hi|lo concat-K)

// EMA / loss constants
#define DECAY_F 0.99f
#define OMD_F ((float)(1.0 - 0.99))
#define EPS_F 1e-5f
#define KEPS_F 0.08192f

#define MARGIN 0.015625f       // 1/64 — >=100x the bf16-split dot error
#define CAP 2048

// -------- scratch (device globals; no allocation allowed) --------
__device__ __align__(16) unsigned long long g_keys[T_TOK];
__device__ __align__(16) float g_stok[T_TOK];
__device__ __align__(16) float g_hcode[K_CODE];
__device__ __align__(16) float g_counts[K_CODE];
__device__ __align__(16) float g_embed_sum[(size_t)K_CODE * C_DIM];
__device__ __align__(16) __nv_bfloat16 g_A2h[(size_t)T_TOK * KSPLIT];   // [hiZ|hiZ|loZ]
__device__ __align__(16) __nv_bfloat16 g_B2h[(size_t)K_CODE * KSPLIT];  // [hiE|loE|hiE]
__device__ __align__(16) float g_dist[(size_t)T_TOK * K_CODE];          // 256 MB approx dists
__device__ double g_loss;
__device__ float g_nsum;

// ------------------------------------------------------------------
// helpers
// ------------------------------------------------------------------
__device__ __forceinline__ uint32_t smem_u32(const void* p) {
    uint32_t a;
    asm("{ .reg .u64 t; cvta.to.shared.u64 t, %1; cvt.u32.u64 %0, t; }"
        : "=r"(a) : "l"(p));
    return a;
}
__device__ __forceinline__ unsigned f2ord(float f) {
    unsigned u = __float_as_uint(f);
    return (u & 0x80000000u) ? ~u : (u | 0x80000000u);
}

// ------------------------------------------------------------------
// K0: init scratch
// ------------------------------------------------------------------
__global__ void k_init() {
    size_t i = (size_t)blockIdx.x * blockDim.x + threadIdx.x;
    size_t stride = (size_t)gridDim.x * blockDim.x;
    float4 z4 = make_float4(0.f, 0.f, 0.f, 0.f);
    float4* es4 = (float4*)g_embed_sum;
    const size_t n4 = (size_t)K_CODE * C_DIM / 4;
    for (size_t j = i; j < n4; j += stride) es4[j] = z4;
    for (size_t j = i; j < K_CODE; j += stride) g_counts[j] = 0.f;
    for (size_t j = i; j < T_TOK; j += stride) g_keys[j] = ~0ull;
    if (i == 0) { g_loss = 0.0; g_nsum = 0.f; }
}

// ------------------------------------------------------------------
// K1: row norms (full fp32 — identical to the R5-passing kernel)
// ------------------------------------------------------------------
__global__ void k_norms(const float* __restrict__ Z, const float* __restrict__ E) {
    int warp = (int)((blockIdx.x * blockDim.x + threadIdx.x) >> 5);
    int lane = threadIdx.x & 31;
    if (warp >= T_TOK + K_CODE) return;
    const float* p = (warp < T_TOK) ? (Z + (size_t)warp * C_DIM)
                                    : (E + (size_t)(warp - T_TOK) * C_DIM);
    const float4* p4 = (const float4*)p;
    float s = 0.f;
#pragma unroll
    for (int i = 0; i < C_DIM / 128; i++) {
        float4 v = p4[lane + i * 32];
        s += v.x * v.x + v.y * v.y + v.z * v.z + v.w * v.w;
    }
#pragma unroll
    for (int off = 16; off; off >>= 1) s += __shfl_xor_sync(0xFFFFFFFFu, s, off);
    if (lane == 0) {
        if (warp < T_TOK) g_stok[warp] = s;
        else              g_hcode[warp - T_TOK] = s;
    }
}

// ------------------------------------------------------------------
// K1b: bf16 hi/lo split with concatenated K:
//   A2h[t] = [hiZ | hiZ | loZ],  B2h[n] = [hiE | loE | hiE]
//   -> sum over K'=1536 = hiZ*hiE + hiZ*loE + loZ*hiE  (err ~1e-5 worst)
// ------------------------------------------------------------------
__global__ void k_split(const float* __restrict__ Z, const float* __restrict__ E) {
    size_t i = (size_t)blockIdx.x * blockDim.x + threadIdx.x;
    if (i >= (size_t)T_TOK * C_DIM) return;
    size_t t = i >> 9, k = i & 511;
    size_t base = t * KSPLIT + k;
    float z = Z[i];
    __nv_bfloat16 zh = __float2bfloat16(z);
    __nv_bfloat16 zl = __float2bfloat16(z - __bfloat162float(zh));
    g_A2h[base] = zh; g_A2h[base + 512] = zh; g_A2h[base + 1024] = zl;
    float e = E[i];
    __nv_bfloat16 eh = __float2bfloat16(e);
    __nv_bfloat16 el = __float2bfloat16(e - __bfloat162float(eh));
    g_B2h[base] = eh; g_B2h[base + 512] = el; g_B2h[base + 1024] = eh;
}

// ------------------------------------------------------------------
// K2: bf16 mma.sync GEMM (A2h @ B2h^T over K'=1536) -> approx dist matrix.
//   CTA 256x128, 512 threads, warp grid 4(M)x4(N), warp tile 64x32.
//   mma.m16n8k16.bf16, BK=32 bf16, 2-stage cp.async.
//   SMEM row stride 40 bf16 (80B): fragment b32 LDS are conflict-free
//   (banks (20g+t)%32 all distinct).
// ------------------------------------------------------------------
#define TILE_M 256
#define TILE_N 128
#define BKB 32
#define RST 40
#define STAGE_BF ((TILE_M + TILE_N) * RST)      // 15360 bf16
#define SMEMB (2 * STAGE_BF * 2)                // 61440 bytes
#define NIT (KSPLIT / BKB)                      // 48

__global__ __launch_bounds__(512, 1) void k_gemm_bf16() {
    extern __shared__ __align__(16) __nv_bfloat16 smb[];
    const uint32_t sm_base = smem_u32(smb);
    const int tid = threadIdx.x;
    const int wid = tid >> 5, lane = tid & 31;
    const int g = lane >> 2, t = lane & 3;
    const int wm = wid >> 2, wn = wid & 3;
    const int bm = blockIdx.y * TILE_M;
    const int bn = blockIdx.x * TILE_N;

    float acc[4][4][4];
#pragma unroll
    for (int a = 0; a < 4; a++)
#pragma unroll
        for (int b = 0; b < 4; b++)
#pragma unroll
            for (int c = 0; c < 4; c++) acc[a][b][c] = 0.f;

    // 1536 16B-chunks per stage (384 rows x 4 segs), 3 per thread
    const __nv_bfloat16* srcp[3];
    uint32_t dsto[3];
#pragma unroll
    for (int i = 0; i < 3; i++) {
        int q = tid + i * 512;
        int row = q >> 2;
        int seg = q & 3;                 // 8 bf16 per 16B segment
        srcp[i] = (row < TILE_M)
                    ? (g_A2h + (size_t)(bm + row) * KSPLIT + seg * 8)
                    : (g_B2h + (size_t)(bn + (row - TILE_M)) * KSPLIT + seg * 8);
        dsto[i] = (uint32_t)(row * RST + seg * 8) * 2u;
    }

    auto load_stage = [&](int c) {
        uint32_t buf = (uint32_t)(c & 1) * (STAGE_BF * 2u);
#pragma unroll
        for (int i = 0; i < 3; i++) {
            asm volatile("cp.async.cg.shared.global [%0], [%1], 16;"
                         :: "r"(sm_base + buf + dsto[i]),
                            "l"(srcp[i] + (size_t)c * BKB) : "memory");
        }
        asm volatile("cp.async.commit_group;" ::: "memory");
    };

    load_stage(0);

    for (int c = 0; c < NIT; c++) {
        if (c + 1 < NIT) load_stage(c + 1);
        if (c + 1 < NIT) asm volatile("cp.async.wait_group 1;" ::: "memory");
        else             asm volatile("cp.async.wait_group 0;" ::: "memory");
        __syncthreads();

        const __nv_bfloat16* Sb = smb + (size_t)(c & 1) * STAGE_BF;
        const __nv_bfloat16* Bsb = Sb + TILE_M * RST;

#pragma unroll
        for (int ks = 0; ks < 2; ks++) {
            const int k0 = ks * 16;
            uint32_t af[4][4];
#pragma unroll
            for (int mf = 0; mf < 4; mf++) {
                const __nv_bfloat16* pr = Sb + (wm * 64 + mf * 16 + g) * RST + k0 + 2 * t;
                af[mf][0] = *(const uint32_t*)(pr);
                af[mf][1] = *(const uint32_t*)(pr + 8 * RST);
                af[mf][2] = *(const uint32_t*)(pr + 8);
                af[mf][3] = *(const uint32_t*)(pr + 8 * RST + 8);
            }
            uint32_t bfr[4][2];
#pragma unroll
            for (int nf = 0; nf < 4; nf++) {
                const __nv_bfloat16* pb = Bsb + (wn * 32 + nf * 8 + g) * RST + k0 + 2 * t;
                bfr[nf][0] = *(const uint32_t*)(pb);
                bfr[nf][1] = *(const uint32_t*)(pb + 8);
            }
#pragma unroll
            for (int mf = 0; mf < 4; mf++)
#pragma unroll
                for (int nf = 0; nf < 4; nf++) {
                    float* d = acc[mf][nf];
                    asm volatile(
                        "mma.sync.aligned.m16n8k16.row.col.f32.bf16.bf16.f32 "
                        "{%0,%1,%2,%3}, {%4,%5,%6,%7}, {%8,%9}, {%0,%1,%2,%3};"
                        : "+f"(d[0]), "+f"(d[1]), "+f"(d[2]), "+f"(d[3])
                        : "r"(af[mf][0]), "r"(af[mf][1]), "r"(af[mf][2]), "r"(af[mf][3]),
                          "r"(bfr[nf][0]), "r"(bfr[nf][1]));
                }
        }
        __syncthreads();
    }

    // ---- epilogue: write approx dist matrix ----
    // acc d0=D[g][2t], d1=D[g][2t+1], d2=D[g+8][2t], d3=D[g+8][2t+1]
#pragma unroll
    for (int mf = 0; mf < 4; mf++) {
        int r0 = bm + wm * 64 + mf * 16 + g;
        float s0 = g_stok[r0];
        float s1 = g_stok[r0 + 8];
#pragma unroll
        for (int nf = 0; nf < 4; nf++) {
            int c0 = bn + wn * 32 + nf * 8 + 2 * t;
            float h0 = g_hcode[c0];
            float h1 = g_hcode[c0 + 1];
            const float* d = acc[mf][nf];
            float2 v0 = make_float2((s0 - 2.0f * d[0]) + h0, (s0 - 2.0f * d[1]) + h1);
            float2 v1 = make_float2((s1 - 2.0f * d[2]) + h0, (s1 - 2.0f * d[3]) + h1);
            *(float2*)(g_dist + (size_t)r0 * K_CODE + c0) = v0;
            *(float2*)(g_dist + (size_t)(r0 + 8) * K_CODE + c0) = v1;
        }
    }
}

// ------------------------------------------------------------------
// K2b: exact re-check. One block (256 thr) per token:
//   scan approx dists -> min; band = {j : d_j < min + MARGIN};
//   for band members recompute dist with the EXACT R5 operation order
//   (sequential-k fmaf, (s - 2*acc) + h, u64 key, atomicMin)
//   -> g_keys bit-identical to the R5-passing kernel.
// ------------------------------------------------------------------
__global__ __launch_bounds__(256) void k_recheck(const float* __restrict__ Z,
                                                 const float* __restrict__ E) {
    __shared__ float wmin[8];
    __shared__ int s_cnt;
    __shared__ int s_list[CAP];
    const int t = blockIdx.x;
    const int tid = threadIdx.x;
    const float* drow = g_dist + (size_t)t * K_CODE;

    if (tid == 0) s_cnt = 0;
    float m = 3.4e38f;
    for (int j = tid; j < K_CODE; j += 256) m = fminf(m, drow[j]);
#pragma unroll
    for (int off = 16; off; off >>= 1) m = fminf(m, __shfl_xor_sync(0xFFFFFFFFu, m, off));
    if ((tid & 31) == 0) wmin[tid >> 5] = m;
    __syncthreads();
    float thr;
    {
        float mm = wmin[0];
#pragma unroll
        for (int w = 1; w < 8; w++) mm = fminf(mm, wmin[w]);
        thr = mm + MARGIN;
    }

    for (int j = tid; j < K_CODE; j += 256) {
        if (drow[j] < thr) {
            int p = atomicAdd(&s_cnt, 1);
            if (p < CAP) s_list[p] = j;
        }
    }
    __syncthreads();

    const float s_tok = g_stok[t];
    const float* zp = Z + (size_t)t * C_DIM;
    const int n = s_cnt;
    unsigned long long best = ~0ull;

    auto proc = [&](int j) {
        const float* ep = E + (size_t)j * C_DIM;
        float a = 0.f;
#pragma unroll 8
        for (int k = 0; k < C_DIM; k++) a = fmaf(zp[k], ep[k], a);  // sequential chain
        float dist = (s_tok - 2.0f * a) + g_hcode[j];
        unsigned long long key = ((unsigned long long)f2ord(dist) << 32) | (unsigned)j;
        best = (key < best) ? key : best;
    };

    if (n <= CAP) {
        for (int i = tid; i < n; i += 256) proc(s_list[i]);
    } else {
        for (int j = tid; j < K_CODE; j += 256)
            if (drow[j] < thr) proc(j);
    }
    if (best != ~0ull) atomicMin(&g_keys[t], best);
}

// ------------------------------------------------------------------
// K3: per-token: gather z_q, straight-through out, loss, counts,
//     embed_sum scatter. One block (128 threads) per token.
// ------------------------------------------------------------------
__global__ void k_token(const float* __restrict__ Z, const float* __restrict__ E,
                        float* __restrict__ out_zq, float* __restrict__ out_idx) {
    __shared__ float red[4];
    const int t = blockIdx.x;
    const int idx = (int)(g_keys[t] & 0xFFFFFFFFull);
    const float4* z4 = (const float4*)(Z + (size_t)t * C_DIM);
    const float4* e4 = (const float4*)(E + (size_t)idx * C_DIM);
    float4* o4 = (float4*)(out_zq + (size_t)t * C_DIM);
    float* es = g_embed_sum + (size_t)idx * C_DIM;

    const int i = threadIdx.x;
    float4 zv = z4[i];
    float4 ev = e4[i];
    float4 o;
    o.x = zv.x + (ev.x - zv.x);
    o.y = zv.y + (ev.y - zv.y);
    o.z = zv.z + (ev.z - zv.z);
    o.w = zv.w + (ev.w - zv.w);
    o4[i] = o;
    float dx = zv.x - ev.x, dy = zv.y - ev.y, dz = zv.z - ev.z, dw = zv.w - ev.w;
    float lsum = dx * dx + dy * dy + dz * dz + dw * dw;

    atomicAdd(&es[4 * i + 0], zv.x);
    atomicAdd(&es[4 * i + 1], zv.y);
    atomicAdd(&es[4 * i + 2], zv.z);
    atomicAdd(&es[4 * i + 3], zv.w);

#pragma unroll
    for (int off = 16; off; off >>= 1) lsum += __shfl_xor_sync(0xFFFFFFFFu, lsum, off);
    if ((i & 31) == 0) red[i >> 5] = lsum;
    __syncthreads();
    if (i == 0) {
        float tot = red[0] + red[1] + red[2] + red[3];
        out_idx[t] = (float)idx;
        atomicAdd(&g_counts[idx], 1.0f);
        atomicAdd(&g_loss, (double)tot);
    }
}

// ------------------------------------------------------------------
// K4: new_cluster_size + its global sum
// ------------------------------------------------------------------
__global__ void k_cluster(const float* __restrict__ cs, float* __restrict__ out_cs) {
    __shared__ float red[8];
    int k = blockIdx.x * 256 + threadIdx.x;
    float v = cs[k] * DECAY_F + g_counts[k] * OMD_F;
    out_cs[k] = v;
    float sum = v;
#pragma unroll
    for (int off = 16; off; off >>= 1) sum += __shfl_xor_sync(0xFFFFFFFFu, sum, off);
    if ((threadIdx.x & 31) == 0) red[threadIdx.x >> 5] = sum;
    __syncthreads();
    if (threadIdx.x == 0) {
        float tot = 0.f;
#pragma unroll
        for (int w = 0; w < 8; w++) tot += red[w];
        atomicAdd(&g_nsum, tot);
    }
}

// ------------------------------------------------------------------
// K5: new_embed_avg, new_codebook, vq_loss scalar.
// ------------------------------------------------------------------
__global__ void k_final(const float* __restrict__ ea, const float* __restrict__ ncs_arr,
                        float* __restrict__ out_cb, float* __restrict__ out_ea,
                        float* __restrict__ out_loss) {
    const int k = blockIdx.x;
    if (k == 0 && threadIdx.x == 0) {
        out_loss[0] = 0.25f * (float)(g_loss / (double)((size_t)T_TOK * C_DIM));
    }
    float n = fmaxf(g_nsum, 1.0f);
    float ncs = ncs_arr[k];
    float sm = (ncs + EPS_F) / (n + KEPS_F) * n;

    const float4* a4 = (const float4*)(ea + (size_t)k * C_DIM);
    const float4* s4 = (const float4*)(g_embed_sum + (size_t)k * C_DIM);
    const int i = threadIdx.x;
    float4 av = a4[i];
    float4 sv = s4[i];
    float ne[4];
    ne[0] = av.x * DECAY_F + sv.x * OMD_F;
    ne[1] = av.y * DECAY_F + sv.y * OMD_F;
    ne[2] = av.z * DECAY_F + sv.z * OMD_F;
    ne[3] = av.w * DECAY_F + sv.w * OMD_F;
    size_t base = (size_t)k * C_DIM + 4 * i;
#pragma unroll
    for (int j = 0; j < 4; j++) {
        out_ea[base + j] = ne[j];
        out_cb[base + j] = ne[j] / sm;   // out offsets are 1 mod 4 -> scalar stores
    }
}

// ------------------------------------------------------------------
// launch
// ------------------------------------------------------------------
extern "C" void kernel_launch(void* const* d_in, const int* in_sizes, int n_in,
                              void* d_out, int out_size) {
    const float* Z  = (const float*)d_in[0];
    const float* E  = (const float*)d_in[1];
    const float* CS = (const float*)d_in[2];
    const float* EA = (const float*)d_in[3];

    float* out = (float*)d_out;
    float* out_zq   = out;
    float* out_idx  = out_zq + (size_t)T_TOK * C_DIM;
    float* out_loss = out_idx + T_TOK;
    float* out_cb   = out_loss + 1;
    float* out_cs   = out_cb + (size_t)K_CODE * C_DIM;
    float* out_ea   = out_cs + K_CODE;

    cudaFuncSetAttribute(k_gemm_bf16, cudaFuncAttributeMaxDynamicSharedMemorySize, SMEMB);

    k_init<<<2048, 256>>>();
    k_norms<<<(T_TOK + K_CODE) / 8, 256>>>(Z, E);
    k_split<<<(T_TOK * C_DIM) / 256, 256>>>(Z, E);
    dim3 grid(K_CODE / TILE_N, T_TOK / TILE_M);   // (64, 32)
    k_gemm_bf16<<<grid, 512, SMEMB>>>();
    k_recheck<<<T_TOK, 256>>>(Z, E);
    k_token<<<T_TOK, 128>>>(Z, E, out_zq, out_idx);
    k_cluster<<<K_CODE / 256, 256>>>(CS, out_cs);
    k_final<<<K_CODE, 128>>>(EA, out_cs, out_cb, out_ea, out_loss);
}

// round 9
// speedup vs baseline: 2.0132x; 1.3649x over previous
#include <cuda_runtime.h>
#include <cuda_bf16.h>
#include <cstdint>

// Problem constants
#define T_TOK 8192
#define K_CODE 8192
#define C_DIM 512
#define KSPLIT 1024            // 2 * C_DIM (bf16 2-term split: hiZ·(hiE+loE))

// EMA / loss constants
#define DECAY_F 0.99f
#define OMD_F ((float)(1.0 - 0.99))
#define EPS_F 1e-5f
#define KEPS_F 0.08192f

#define MARGIN 0.03125f        // 1/32 — >=5x the 2-term split dist error tail
#define CAP 2048

// -------- scratch (device globals; no allocation allowed) --------
__device__ __align__(16) unsigned long long g_keys[T_TOK];
__device__ __align__(16) unsigned g_amin[T_TOK];                        // approx-min dist bits
__device__ __align__(16) float g_stok[T_TOK];
__device__ __align__(16) float g_hcode[K_CODE];
__device__ __align__(16) float g_counts[K_CODE];
__device__ __align__(16) float g_embed_sum[(size_t)K_CODE * C_DIM];
__device__ __align__(16) __nv_bfloat16 g_A2h[(size_t)T_TOK * KSPLIT];   // [hiZ|hiZ]
__device__ __align__(16) __nv_bfloat16 g_B2h[(size_t)K_CODE * KSPLIT];  // [hiE|loE]
__device__ __align__(16) float g_dist[(size_t)T_TOK * K_CODE];          // approx dists
__device__ double g_loss;
__device__ float g_nsum;

// ------------------------------------------------------------------
// helpers
// ------------------------------------------------------------------
__device__ __forceinline__ uint32_t smem_u32(const void* p) {
    uint32_t a;
    asm("{ .reg .u64 t; cvta.to.shared.u64 t, %1; cvt.u32.u64 %0, t; }"
        : "=r"(a) : "l"(p));
    return a;
}
__device__ __forceinline__ unsigned f2ord(float f) {
    unsigned u = __float_as_uint(f);
    return (u & 0x80000000u) ? ~u : (u | 0x80000000u);
}

#define LDSM_X4(r0, r1, r2, r3, addr) \
    asm volatile("ldmatrix.sync.aligned.m8n8.x4.shared.b16 {%0,%1,%2,%3}, [%4];" \
                 : "=r"(r0), "=r"(r1), "=r"(r2), "=r"(r3) : "r"(addr))

// ------------------------------------------------------------------
// K0: init scratch
// ------------------------------------------------------------------
__global__ void k_init() {
    size_t i = (size_t)blockIdx.x * blockDim.x + threadIdx.x;
    size_t stride = (size_t)gridDim.x * blockDim.x;
    float4 z4 = make_float4(0.f, 0.f, 0.f, 0.f);
    float4* es4 = (float4*)g_embed_sum;
    const size_t n4 = (size_t)K_CODE * C_DIM / 4;
    for (size_t j = i; j < n4; j += stride) es4[j] = z4;
    for (size_t j = i; j < K_CODE; j += stride) g_counts[j] = 0.f;
    for (size_t j = i; j < T_TOK; j += stride) { g_keys[j] = ~0ull; g_amin[j] = 0xFFFFFFFFu; }
    if (i == 0) { g_loss = 0.0; g_nsum = 0.f; }
}

// ------------------------------------------------------------------
// K1: row norms (full fp32 — identical to the R5-passing kernel)
// ------------------------------------------------------------------
__global__ void k_norms(const float* __restrict__ Z, const float* __restrict__ E) {
    int warp = (int)((blockIdx.x * blockDim.x + threadIdx.x) >> 5);
    int lane = threadIdx.x & 31;
    if (warp >= T_TOK + K_CODE) return;
    const float* p = (warp < T_TOK) ? (Z + (size_t)warp * C_DIM)
                                    : (E + (size_t)(warp - T_TOK) * C_DIM);
    const float4* p4 = (const float4*)p;
    float s = 0.f;
#pragma unroll
    for (int i = 0; i < C_DIM / 128; i++) {
        float4 v = p4[lane + i * 32];
        s += v.x * v.x + v.y * v.y + v.z * v.z + v.w * v.w;
    }
#pragma unroll
    for (int off = 16; off; off >>= 1) s += __shfl_xor_sync(0xFFFFFFFFu, s, off);
    if (lane == 0) {
        if (warp < T_TOK) g_stok[warp] = s;
        else              g_hcode[warp - T_TOK] = s;
    }
}

// ------------------------------------------------------------------
// K1b: bf16 2-term split, concatenated K:
//   A2h[t] = [hiZ | hiZ],  B2h[n] = [hiE | loE]
//   -> sum over K'=1024 = hiZ*(hiE+loE) ≈ hiZ*E ; dropped loZ*E ~5e-4 std
// ------------------------------------------------------------------
__global__ void k_split(const float* __restrict__ Z, const float* __restrict__ E) {
    size_t i = (size_t)blockIdx.x * blockDim.x + threadIdx.x;
    if (i >= (size_t)T_TOK * C_DIM) return;
    size_t t = i >> 9, k = i & 511;
    size_t base = t * KSPLIT + k;
    float z = Z[i];
    __nv_bfloat16 zh = __float2bfloat16(z);
    g_A2h[base] = zh; g_A2h[base + 512] = zh;
    float e = E[i];
    __nv_bfloat16 eh = __float2bfloat16(e);
    __nv_bfloat16 el = __float2bfloat16(e - __bfloat162float(eh));
    g_B2h[base] = eh; g_B2h[base + 512] = el;
}

// ------------------------------------------------------------------
// K2: bf16 mma.sync GEMM (A2h @ B2h^T over K'=1024) -> approx dists + row minima.
//   CTA 256x128, 512 threads, warp grid 4(M)x4(N), warp tile 64x32.
//   mma.m16n8k16.bf16, BKB=32, ldmatrix.x4 fragments, 3-stage cp.async,
//   ONE __syncthreads per chunk. SMEM row stride 40 bf16 -> LDSM conflict-free.
// ------------------------------------------------------------------
#define TILE_M 256
#define TILE_N 128
#define BKB 32
#define RST 40
#define STAGE_BF ((TILE_M + TILE_N) * RST)      // 15360 bf16
#define STAGE_BYTES (STAGE_BF * 2)              // 30720
#define SMEMB (3 * STAGE_BYTES)                 // 92160
#define NIT (KSPLIT / BKB)                      // 32

__global__ __launch_bounds__(512, 1) void k_gemm_bf16() {
    extern __shared__ __align__(16) __nv_bfloat16 smb[];
    const uint32_t sm_base = smem_u32(smb);
    const int tid = threadIdx.x;
    const int wid = tid >> 5, lane = tid & 31;
    const int g = lane >> 2, t = lane & 3;
    const int wm = wid >> 2, wn = wid & 3;
    const int bm = blockIdx.y * TILE_M;
    const int bn = blockIdx.x * TILE_N;

    float acc[4][4][4];
#pragma unroll
    for (int a = 0; a < 4; a++)
#pragma unroll
        for (int b = 0; b < 4; b++)
#pragma unroll
            for (int c = 0; c < 4; c++) acc[a][b][c] = 0.f;

    // cp.async mapping: 1536 16B-chunks per stage (384 rows x 4 segs), 3/thread
    const __nv_bfloat16* srcp[3];
    uint32_t dsto[3];
#pragma unroll
    for (int i = 0; i < 3; i++) {
        int q = tid + i * 512;
        int row = q >> 2;
        int seg = q & 3;                 // 8 bf16 per 16B segment
        srcp[i] = (row < TILE_M)
                    ? (g_A2h + (size_t)(bm + row) * KSPLIT + seg * 8)
                    : (g_B2h + (size_t)(bn + (row - TILE_M)) * KSPLIT + seg * 8);
        dsto[i] = (uint32_t)(row * RST + seg * 8) * 2u;
    }

    auto load_stage = [&](int c) {
        uint32_t buf = (uint32_t)(c % 3) * STAGE_BYTES;
#pragma unroll
        for (int i = 0; i < 3; i++) {
            asm volatile("cp.async.cg.shared.global [%0], [%1], 16;"
                         :: "r"(sm_base + buf + dsto[i]),
                            "l"(srcp[i] + (size_t)c * BKB) : "memory");
        }
        asm volatile("cp.async.commit_group;" ::: "memory");
    };

    // ldmatrix per-lane element offsets (in bf16 elements, within a stage)
    const int lrow = lane & 7, blk = lane >> 3;
    const uint32_t a_elem = (uint32_t)((wm * 64 + (blk & 1) * 8 + lrow) * RST + (blk >> 1) * 8);
    const uint32_t b_elem = (uint32_t)((TILE_M + wn * 32 + (blk >> 1) * 8 + lrow) * RST + (blk & 1) * 8);

    load_stage(0);
    load_stage(1);

    for (int c = 0; c < NIT; c++) {
        if (c + 1 < NIT) asm volatile("cp.async.wait_group 1;" ::: "memory");
        else             asm volatile("cp.async.wait_group 0;" ::: "memory");
        __syncthreads();                 // all warps past compute of stage c-1
        if (c + 2 < NIT) load_stage(c + 2);

        const uint32_t sbuf = sm_base + (uint32_t)(c % 3) * STAGE_BYTES;

#pragma unroll
        for (int ks = 0; ks < 2; ks++) {
            const uint32_t k0 = ks * 16;
            uint32_t af[4][4];
#pragma unroll
            for (int mf = 0; mf < 4; mf++) {
                uint32_t addr = sbuf + (a_elem + (uint32_t)(mf * 16 * RST) + k0) * 2u;
                LDSM_X4(af[mf][0], af[mf][1], af[mf][2], af[mf][3], addr);
            }
            uint32_t bfr[4][2];
#pragma unroll
            for (int nfp = 0; nfp < 2; nfp++) {
                uint32_t addr = sbuf + (b_elem + (uint32_t)(nfp * 16 * RST) + k0) * 2u;
                LDSM_X4(bfr[2 * nfp][0], bfr[2 * nfp][1],
                        bfr[2 * nfp + 1][0], bfr[2 * nfp + 1][1], addr);
            }
#pragma unroll
            for (int mf = 0; mf < 4; mf++)
#pragma unroll
                for (int nf = 0; nf < 4; nf++) {
                    float* d = acc[mf][nf];
                    asm volatile(
                        "mma.sync.aligned.m16n8k16.row.col.f32.bf16.bf16.f32 "
                        "{%0,%1,%2,%3}, {%4,%5,%6,%7}, {%8,%9}, {%0,%1,%2,%3};"
                        : "+f"(d[0]), "+f"(d[1]), "+f"(d[2]), "+f"(d[3])
                        : "r"(af[mf][0]), "r"(af[mf][1]), "r"(af[mf][2]), "r"(af[mf][3]),
                          "r"(bfr[nf][0]), "r"(bfr[nf][1]));
                }
        }
    }

    // ---- epilogue: write approx dists + per-row approx minima ----
    // acc d0=D[g][2t], d1=D[g][2t+1], d2=D[g+8][2t], d3=D[g+8][2t+1]
#pragma unroll
    for (int mf = 0; mf < 4; mf++) {
        int r0 = bm + wm * 64 + mf * 16 + g;
        float s0 = g_stok[r0];
        float s1 = g_stok[r0 + 8];
        float m0 = 3.4e38f, m1 = 3.4e38f;
#pragma unroll
        for (int nf = 0; nf < 4; nf++) {
            int c0 = bn + wn * 32 + nf * 8 + 2 * t;
            float h0 = g_hcode[c0];
            float h1 = g_hcode[c0 + 1];
            const float* d = acc[mf][nf];
            float2 v0 = make_float2((s0 - 2.0f * d[0]) + h0, (s0 - 2.0f * d[1]) + h1);
            float2 v1 = make_float2((s1 - 2.0f * d[2]) + h0, (s1 - 2.0f * d[3]) + h1);
            *(float2*)(g_dist + (size_t)r0 * K_CODE + c0) = v0;
            *(float2*)(g_dist + (size_t)(r0 + 8) * K_CODE + c0) = v1;
            m0 = fminf(m0, fminf(v0.x, v0.y));
            m1 = fminf(m1, fminf(v1.x, v1.y));
        }
#pragma unroll
        for (int off = 1; off <= 2; off <<= 1) {
            m0 = fminf(m0, __shfl_xor_sync(0xFFFFFFFFu, m0, off));
            m1 = fminf(m1, __shfl_xor_sync(0xFFFFFFFFu, m1, off));
        }
        if (t == 0) {
            atomicMin(&g_amin[r0], __float_as_uint(m0));       // positive floats: bits ordered
            atomicMin(&g_amin[r0 + 8], __float_as_uint(m1));
        }
    }
}

// ------------------------------------------------------------------
// K2b: exact re-check. One block (256 thr) per token — SINGLE pass:
//   thr = approx_min + MARGIN; band members recomputed with the EXACT
//   R5 operation order (sequential-k fmaf, (s-2*acc)+h, u64 key, atomicMin)
//   -> g_keys bit-identical to the R5-passing kernel.
// ------------------------------------------------------------------
__global__ __launch_bounds__(256) void k_recheck(const float* __restrict__ Z,
                                                 const float* __restrict__ E) {
    __shared__ int s_cnt;
    __shared__ int s_list[CAP];
    const int t = blockIdx.x;
    const int tid = threadIdx.x;
    const float* drow = g_dist + (size_t)t * K_CODE;

    if (tid == 0) s_cnt = 0;
    __syncthreads();
    const float thr = __uint_as_float(g_amin[t]) + MARGIN;

    for (int j = tid; j < K_CODE; j += 256) {
        if (drow[j] < thr) {
            int p = atomicAdd(&s_cnt, 1);
            if (p < CAP) s_list[p] = j;
        }
    }
    __syncthreads();

    const float s_tok = g_stok[t];
    const float* zp = Z + (size_t)t * C_DIM;
    const int n = s_cnt;
    unsigned long long best = ~0ull;

    auto proc = [&](int j) {
        const float* ep = E + (size_t)j * C_DIM;
        float a = 0.f;
#pragma unroll 8
        for (int k = 0; k < C_DIM; k++) a = fmaf(zp[k], ep[k], a);  // sequential chain
        float dist = (s_tok - 2.0f * a) + g_hcode[j];
        unsigned long long key = ((unsigned long long)f2ord(dist) << 32) | (unsigned)j;
        best = (key < best) ? key : best;
    };

    if (n <= CAP) {
        for (int i = tid; i < n; i += 256) proc(s_list[i]);
    } else {
        for (int j = tid; j < K_CODE; j += 256)
            if (drow[j] < thr) proc(j);
    }
    if (best != ~0ull) atomicMin(&g_keys[t], best);
}

// ------------------------------------------------------------------
// K3: per-token: gather z_q, straight-through out, loss, counts,
//     embed_sum scatter. One block (128 threads) per token.
// ------------------------------------------------------------------
__global__ void k_token(const float* __restrict__ Z, const float* __restrict__ E,
                        float* __restrict__ out_zq, float* __restrict__ out_idx) {
    __shared__ float red[4];
    const int t = blockIdx.x;
    const int idx = (int)(g_keys[t] & 0xFFFFFFFFull);
    const float4* z4 = (const float4*)(Z + (size_t)t * C_DIM);
    const float4* e4 = (const float4*)(E + (size_t)idx * C_DIM);
    float4* o4 = (float4*)(out_zq + (size_t)t * C_DIM);
    float* es = g_embed_sum + (size_t)idx * C_DIM;

    const int i = threadIdx.x;
    float4 zv = z4[i];
    float4 ev = e4[i];
    float4 o;
    o.x = zv.x + (ev.x - zv.x);
    o.y = zv.y + (ev.y - zv.y);
    o.z = zv.z + (ev.z - zv.z);
    o.w = zv.w + (ev.w - zv.w);
    o4[i] = o;
    float dx = zv.x - ev.x, dy = zv.y - ev.y, dz = zv.z - ev.z, dw = zv.w - ev.w;
    float lsum = dx * dx + dy * dy + dz * dz + dw * dw;

    atomicAdd(&es[4 * i + 0], zv.x);
    atomicAdd(&es[4 * i + 1], zv.y);
    atomicAdd(&es[4 * i + 2], zv.z);
    atomicAdd(&es[4 * i + 3], zv.w);

#pragma unroll
    for (int off = 16; off; off >>= 1) lsum += __shfl_xor_sync(0xFFFFFFFFu, lsum, off);
    if ((i & 31) == 0) red[i >> 5] = lsum;
    __syncthreads();
    if (i == 0) {
        float tot = red[0] + red[1] + red[2] + red[3];
        out_idx[t] = (float)idx;
        atomicAdd(&g_counts[idx], 1.0f);
        atomicAdd(&g_loss, (double)tot);
    }
}

// ------------------------------------------------------------------
// K4: new_cluster_size + its global sum
// ------------------------------------------------------------------
__global__ void k_cluster(const float* __restrict__ cs, float* __restrict__ out_cs) {
    __shared__ float red[8];
    int k = blockIdx.x * 256 + threadIdx.x;
    float v = cs[k] * DECAY_F + g_counts[k] * OMD_F;
    out_cs[k] = v;
    float sum = v;
#pragma unroll
    for (int off = 16; off; off >>= 1) sum += __shfl_xor_sync(0xFFFFFFFFu, sum, off);
    if ((threadIdx.x & 31) == 0) red[threadIdx.x >> 5] = sum;
    __syncthreads();
    if (threadIdx.x == 0) {
        float tot = 0.f;
#pragma unroll
        for (int w = 0; w < 8; w++) tot += red[w];
        atomicAdd(&g_nsum, tot);
    }
}

// ------------------------------------------------------------------
// K5: new_embed_avg, new_codebook, vq_loss scalar.
// ------------------------------------------------------------------
__global__ void k_final(const float* __restrict__ ea, const float* __restrict__ ncs_arr,
                        float* __restrict__ out_cb, float* __restrict__ out_ea,
                        float* __restrict__ out_loss) {
    const int k = blockIdx.x;
    if (k == 0 && threadIdx.x == 0) {
        out_loss[0] = 0.25f * (float)(g_loss / (double)((size_t)T_TOK * C_DIM));
    }
    float n = fmaxf(g_nsum, 1.0f);
    float ncs = ncs_arr[k];
    float sm = (ncs + EPS_F) / (n + KEPS_F) * n;

    const float4* a4 = (const float4*)(ea + (size_t)k * C_DIM);
    const float4* s4 = (const float4*)(g_embed_sum + (size_t)k * C_DIM);
    const int i = threadIdx.x;
    float4 av = a4[i];
    float4 sv = s4[i];
    float ne[4];
    ne[0] = av.x * DECAY_F + sv.x * OMD_F;
    ne[1] = av.y * DECAY_F + sv.y * OMD_F;
    ne[2] = av.z * DECAY_F + sv.z * OMD_F;
    ne[3] = av.w * DECAY_F + sv.w * OMD_F;
    size_t base = (size_t)k * C_DIM + 4 * i;
#pragma unroll
    for (int j = 0; j < 4; j++) {
        out_ea[base + j] = ne[j];
        out_cb[base + j] = ne[j] / sm;   // out offsets are 1 mod 4 -> scalar stores
    }
}

// ------------------------------------------------------------------
// launch
// ------------------------------------------------------------------
extern "C" void kernel_launch(void* const* d_in, const int* in_sizes, int n_in,
                              void* d_out, int out_size) {
    const float* Z  = (const float*)d_in[0];
    const float* E  = (const float*)d_in[1];
    const float* CS = (const float*)d_in[2];
    const float* EA = (const float*)d_in[3];

    float* out = (float*)d_out;
    float* out_zq   = out;
    float* out_idx  = out_zq + (size_t)T_TOK * C_DIM;
    float* out_loss = out_idx + T_TOK;
    float* out_cb   = out_loss + 1;
    float* out_cs   = out_cb + (size_t)K_CODE * C_DIM;
    float* out_ea   = out_cs + K_CODE;

    cudaFuncSetAttribute(k_gemm_bf16, cudaFuncAttributeMaxDynamicSharedMemorySize, SMEMB);

    k_init<<<2048, 256>>>();
    k_norms<<<(T_TOK + K_CODE) / 8, 256>>>(Z, E);
    k_split<<<(T_TOK * C_DIM) / 256, 256>>>(Z, E);
    dim3 grid(K_CODE / TILE_N, T_TOK / TILE_M);   // (64, 32)
    k_gemm_bf16<<<grid, 512, SMEMB>>>();
    k_recheck<<<T_TOK, 256>>>(Z, E);
    k_token<<<T_TOK, 128>>>(Z, E, out_zq, out_idx);
    k_cluster<<<K_CODE / 256, 256>>>(CS, out_cs);
    k_final<<<K_CODE, 128>>>(EA, out_cs, out_cb, out_ea, out_loss);
}

// round 10
// speedup vs baseline: 2.9688x; 1.4746x over previous
#include <cuda_runtime.h>
#include <cuda_bf16.h>
#include <cstdint>

// Problem constants
#define T_TOK 8192
#define K_CODE 8192
#define C_DIM 512
#define KSPLIT 512             // plain bf16: hiZ · hiE only

// EMA / loss constants
#define DECAY_F 0.99f
#define OMD_F ((float)(1.0 - 0.99))
#define EPS_F 1e-5f
#define KEPS_F 0.08192f

#define MARGIN 0.125f          // 1/8 — ~89 sigma of the bf16 dist-error model
#define CAP 2048

// -------- scratch (device globals; no allocation allowed) --------
__device__ __align__(16) unsigned long long g_keys[T_TOK];
__device__ __align__(16) unsigned g_amin[T_TOK];                        // approx-min dist bits
__device__ __align__(16) float g_stok[T_TOK];
__device__ __align__(16) float g_hcode[K_CODE];
__device__ __align__(16) float g_counts[K_CODE];
__device__ __align__(16) float g_embed_sum[(size_t)K_CODE * C_DIM];
__device__ __align__(16) __nv_bfloat16 g_A2h[(size_t)T_TOK * KSPLIT];   // bf16(Z)
__device__ __align__(16) __nv_bfloat16 g_B2h[(size_t)K_CODE * KSPLIT];  // bf16(E)
__device__ __align__(16) float g_dist[(size_t)T_TOK * K_CODE];          // approx dists
__device__ double g_loss;
__device__ float g_nsum;

// ------------------------------------------------------------------
// helpers
// ------------------------------------------------------------------
__device__ __forceinline__ uint32_t smem_u32(const void* p) {
    uint32_t a;
    asm("{ .reg .u64 t; cvta.to.shared.u64 t, %1; cvt.u32.u64 %0, t; }"
        : "=r"(a) : "l"(p));
    return a;
}
__device__ __forceinline__ unsigned f2ord(float f) {
    unsigned u = __float_as_uint(f);
    return (u & 0x80000000u) ? ~u : (u | 0x80000000u);
}

#define LDSM_X4(r0, r1, r2, r3, addr) \
    asm volatile("ldmatrix.sync.aligned.m8n8.x4.shared.b16 {%0,%1,%2,%3}, [%4];" \
                 : "=r"(r0), "=r"(r1), "=r"(r2), "=r"(r3) : "r"(addr))

// ------------------------------------------------------------------
// K0: init scratch
// ------------------------------------------------------------------
__global__ void k_init() {
    size_t i = (size_t)blockIdx.x * blockDim.x + threadIdx.x;
    size_t stride = (size_t)gridDim.x * blockDim.x;
    float4 z4 = make_float4(0.f, 0.f, 0.f, 0.f);
    float4* es4 = (float4*)g_embed_sum;
    const size_t n4 = (size_t)K_CODE * C_DIM / 4;
    for (size_t j = i; j < n4; j += stride) es4[j] = z4;
    for (size_t j = i; j < K_CODE; j += stride) g_counts[j] = 0.f;
    for (size_t j = i; j < T_TOK; j += stride) { g_keys[j] = ~0ull; g_amin[j] = 0xFFFFFFFFu; }
    if (i == 0) { g_loss = 0.0; g_nsum = 0.f; }
}

// ------------------------------------------------------------------
// K1: row norms (full fp32 — identical to the R5-passing kernel)
// ------------------------------------------------------------------
__global__ void k_norms(const float* __restrict__ Z, const float* __restrict__ E) {
    int warp = (int)((blockIdx.x * blockDim.x + threadIdx.x) >> 5);
    int lane = threadIdx.x & 31;
    if (warp >= T_TOK + K_CODE) return;
    const float* p = (warp < T_TOK) ? (Z + (size_t)warp * C_DIM)
                                    : (E + (size_t)(warp - T_TOK) * C_DIM);
    const float4* p4 = (const float4*)p;
    float s = 0.f;
#pragma unroll
    for (int i = 0; i < C_DIM / 128; i++) {
        float4 v = p4[lane + i * 32];
        s += v.x * v.x + v.y * v.y + v.z * v.z + v.w * v.w;
    }
#pragma unroll
    for (int off = 16; off; off >>= 1) s += __shfl_xor_sync(0xFFFFFFFFu, s, off);
    if (lane == 0) {
        if (warp < T_TOK) g_stok[warp] = s;
        else              g_hcode[warp - T_TOK] = s;
    }
}

// ------------------------------------------------------------------
// K1b: plain bf16 conversion (K'=512)
// ------------------------------------------------------------------
__global__ void k_split(const float* __restrict__ Z, const float* __restrict__ E) {
    size_t i = (size_t)blockIdx.x * blockDim.x + threadIdx.x;
    if (i >= (size_t)T_TOK * C_DIM) return;
    g_A2h[i] = __float2bfloat16(Z[i]);
    g_B2h[i] = __float2bfloat16(E[i]);
}

// ------------------------------------------------------------------
// K2: bf16 mma.sync GEMM (bf16(Z) @ bf16(E)^T, K'=512) -> approx dists + minima.
//   CTA 128x256, 256 threads, 8 warps (2 M x 4 N), warp tile 64x64.
//   mma.m16n8k16.bf16, BKB=32, ldmatrix.x4, 4-stage cp.async,
//   one __syncthreads per chunk. RST=40 bf16 row stride.
// ------------------------------------------------------------------
#define TILE_M 128
#define TILE_N 256
#define BKB 32
#define RST 40
#define STAGE_BF ((TILE_M + TILE_N) * RST)      // 15360 bf16
#define STAGE_BYTES (STAGE_BF * 2)              // 30720
#define NSTAGE 4
#define SMEMB (NSTAGE * STAGE_BYTES)            // 122880
#define NIT (KSPLIT / BKB)                      // 16

__global__ __launch_bounds__(256, 1) void k_gemm_bf16() {
    extern __shared__ __align__(16) __nv_bfloat16 smb[];
    const uint32_t sm_base = smem_u32(smb);
    const int tid = threadIdx.x;
    const int wid = tid >> 5, lane = tid & 31;
    const int g = lane >> 2, t = lane & 3;
    const int wm = wid >> 2, wn = wid & 3;     // 2 x 4 warp grid
    const int bm = blockIdx.y * TILE_M;
    const int bn = blockIdx.x * TILE_N;

    float acc[4][8][4];
#pragma unroll
    for (int a = 0; a < 4; a++)
#pragma unroll
        for (int b = 0; b < 8; b++)
#pragma unroll
            for (int c = 0; c < 4; c++) acc[a][b][c] = 0.f;

    // cp.async mapping: 1536 16B-chunks per stage (384 rows x 4 segs), 6/thread
    const __nv_bfloat16* srcp[6];
    uint32_t dsto[6];
#pragma unroll
    for (int i = 0; i < 6; i++) {
        int q = tid + i * 256;
        int row = q >> 2;
        int seg = q & 3;                 // 8 bf16 per 16B segment
        srcp[i] = (row < TILE_M)
                    ? (g_A2h + (size_t)(bm + row) * KSPLIT + seg * 8)
                    : (g_B2h + (size_t)(bn + (row - TILE_M)) * KSPLIT + seg * 8);
        dsto[i] = (uint32_t)(row * RST + seg * 8) * 2u;
    }

    auto load_stage = [&](int c) {
        uint32_t buf = (uint32_t)(c % NSTAGE) * STAGE_BYTES;
#pragma unroll
        for (int i = 0; i < 6; i++) {
            asm volatile("cp.async.cg.shared.global [%0], [%1], 16;"
                         :: "r"(sm_base + buf + dsto[i]),
                            "l"(srcp[i] + (size_t)c * BKB) : "memory");
        }
        asm volatile("cp.async.commit_group;" ::: "memory");
    };

    // ldmatrix per-lane element offsets (bf16 elements within a stage)
    const int lrow = lane & 7, blk = lane >> 3;
    const uint32_t a_elem = (uint32_t)((wm * 64 + (blk & 1) * 8 + lrow) * RST + (blk >> 1) * 8);
    uint32_t b_elem[4];
#pragma unroll
    for (int nfp = 0; nfp < 4; nfp++)
        b_elem[nfp] = (uint32_t)((TILE_M + wn * 64 + nfp * 16 + (blk >> 1) * 8 + lrow) * RST
                                 + (blk & 1) * 8);

    load_stage(0);
    load_stage(1);
    load_stage(2);

    for (int c = 0; c < NIT; c++) {
        if (c + 3 < NIT)      asm volatile("cp.async.wait_group 2;" ::: "memory");
        else if (c + 2 < NIT) asm volatile("cp.async.wait_group 2;" ::: "memory");
        else if (c + 1 < NIT) asm volatile("cp.async.wait_group 1;" ::: "memory");
        else                  asm volatile("cp.async.wait_group 0;" ::: "memory");
        __syncthreads();                 // all warps past compute of stage c-1
        if (c + 3 < NIT) load_stage(c + 3);

        const uint32_t sbuf = sm_base + (uint32_t)(c % NSTAGE) * STAGE_BYTES;

#pragma unroll
        for (int ks = 0; ks < 2; ks++) {
            const uint32_t k0 = ks * 16;
            uint32_t af[4][4];
#pragma unroll
            for (int mf = 0; mf < 4; mf++) {
                uint32_t addr = sbuf + (a_elem + (uint32_t)(mf * 16 * RST) + k0) * 2u;
                LDSM_X4(af[mf][0], af[mf][1], af[mf][2], af[mf][3], addr);
            }
            uint32_t bfr[8][2];
#pragma unroll
            for (int nfp = 0; nfp < 4; nfp++) {
                uint32_t addr = sbuf + (b_elem[nfp] + k0) * 2u;
                LDSM_X4(bfr[2 * nfp][0], bfr[2 * nfp][1],
                        bfr[2 * nfp + 1][0], bfr[2 * nfp + 1][1], addr);
            }
#pragma unroll
            for (int mf = 0; mf < 4; mf++)
#pragma unroll
                for (int nf = 0; nf < 8; nf++) {
                    float* d = acc[mf][nf];
                    asm volatile(
                        "mma.sync.aligned.m16n8k16.row.col.f32.bf16.bf16.f32 "
                        "{%0,%1,%2,%3}, {%4,%5,%6,%7}, {%8,%9}, {%0,%1,%2,%3};"
                        : "+f"(d[0]), "+f"(d[1]), "+f"(d[2]), "+f"(d[3])
                        : "r"(af[mf][0]), "r"(af[mf][1]), "r"(af[mf][2]), "r"(af[mf][3]),
                          "r"(bfr[nf][0]), "r"(bfr[nf][1]));
                }
        }
    }

    // ---- epilogue: write approx dists + per-row approx minima ----
    // acc d0=D[g][2t], d1=D[g][2t+1], d2=D[g+8][2t], d3=D[g+8][2t+1]
#pragma unroll
    for (int mf = 0; mf < 4; mf++) {
        int r0 = bm + wm * 64 + mf * 16 + g;
        float s0 = g_stok[r0];
        float s1 = g_stok[r0 + 8];
        float m0 = 3.4e38f, m1 = 3.4e38f;
#pragma unroll
        for (int nf = 0; nf < 8; nf++) {
            int c0 = bn + wn * 64 + nf * 8 + 2 * t;
            float h0 = g_hcode[c0];
            float h1 = g_hcode[c0 + 1];
            const float* d = acc[mf][nf];
            float2 v0 = make_float2((s0 - 2.0f * d[0]) + h0, (s0 - 2.0f * d[1]) + h1);
            float2 v1 = make_float2((s1 - 2.0f * d[2]) + h0, (s1 - 2.0f * d[3]) + h1);
            *(float2*)(g_dist + (size_t)r0 * K_CODE + c0) = v0;
            *(float2*)(g_dist + (size_t)(r0 + 8) * K_CODE + c0) = v1;
            m0 = fminf(m0, fminf(v0.x, v0.y));
            m1 = fminf(m1, fminf(v1.x, v1.y));
        }
#pragma unroll
        for (int off = 1; off <= 2; off <<= 1) {
            m0 = fminf(m0, __shfl_xor_sync(0xFFFFFFFFu, m0, off));
            m1 = fminf(m1, __shfl_xor_sync(0xFFFFFFFFu, m1, off));
        }
        if (t == 0) {
            atomicMin(&g_amin[r0], __float_as_uint(m0));       // positive floats: bits ordered
            atomicMin(&g_amin[r0 + 8], __float_as_uint(m1));
        }
    }
}

// ------------------------------------------------------------------
// K2b: exact re-check. One block (256 thr) per token — SINGLE pass:
//   thr = approx_min + MARGIN; band members recomputed with the EXACT
//   R5 operation order (sequential-k fmaf, (s-2*acc)+h, u64 key, atomicMin)
//   -> g_keys bit-identical to the R5-passing kernel.
// ------------------------------------------------------------------
__global__ __launch_bounds__(256) void k_recheck(const float* __restrict__ Z,
                                                 const float* __restrict__ E) {
    __shared__ int s_cnt;
    __shared__ int s_list[CAP];
    const int t = blockIdx.x;
    const int tid = threadIdx.x;
    const float* drow = g_dist + (size_t)t * K_CODE;

    if (tid == 0) s_cnt = 0;
    __syncthreads();
    const float thr = __uint_as_float(g_amin[t]) + MARGIN;

    for (int j = tid; j < K_CODE; j += 256) {
        if (drow[j] < thr) {
            int p = atomicAdd(&s_cnt, 1);
            if (p < CAP) s_list[p] = j;
        }
    }
    __syncthreads();

    const float s_tok = g_stok[t];
    const float* zp = Z + (size_t)t * C_DIM;
    const int n = s_cnt;
    unsigned long long best = ~0ull;

    auto proc = [&](int j) {
        const float* ep = E + (size_t)j * C_DIM;
        float a = 0.f;
#pragma unroll 8
        for (int k = 0; k < C_DIM; k++) a = fmaf(zp[k], ep[k], a);  // sequential chain
        float dist = (s_tok - 2.0f * a) + g_hcode[j];
        unsigned long long key = ((unsigned long long)f2ord(dist) << 32) | (unsigned)j;
        best = (key < best) ? key : best;
    };

    if (n <= CAP) {
        for (int i = tid; i < n; i += 256) proc(s_list[i]);
    } else {
        for (int j = tid; j < K_CODE; j += 256)
            if (drow[j] < thr) proc(j);
    }
    if (best != ~0ull) atomicMin(&g_keys[t], best);
}

// ------------------------------------------------------------------
// K3: per-token: gather z_q, straight-through out, loss, counts,
//     embed_sum scatter. One block (128 threads) per token.
// ------------------------------------------------------------------
__global__ void k_token(const float* __restrict__ Z, const float* __restrict__ E,
                        float* __restrict__ out_zq, float* __restrict__ out_idx) {
    __shared__ float red[4];
    const int t = blockIdx.x;
    const int idx = (int)(g_keys[t] & 0xFFFFFFFFull);
    const float4* z4 = (const float4*)(Z + (size_t)t * C_DIM);
    const float4* e4 = (const float4*)(E + (size_t)idx * C_DIM);
    float4* o4 = (float4*)(out_zq + (size_t)t * C_DIM);
    float* es = g_embed_sum + (size_t)idx * C_DIM;

    const int i = threadIdx.x;
    float4 zv = z4[i];
    float4 ev = e4[i];
    float4 o;
    o.x = zv.x + (ev.x - zv.x);
    o.y = zv.y + (ev.y - zv.y);
    o.z = zv.z + (ev.z - zv.z);
    o.w = zv.w + (ev.w - zv.w);
    o4[i] = o;
    float dx = zv.x - ev.x, dy = zv.y - ev.y, dz = zv.z - ev.z, dw = zv.w - ev.w;
    float lsum = dx * dx + dy * dy + dz * dz + dw * dw;

    atomicAdd(&es[4 * i + 0], zv.x);
    atomicAdd(&es[4 * i + 1], zv.y);
    atomicAdd(&es[4 * i + 2], zv.z);
    atomicAdd(&es[4 * i + 3], zv.w);

#pragma unroll
    for (int off = 16; off; off >>= 1) lsum += __shfl_xor_sync(0xFFFFFFFFu, lsum, off);
    if ((i & 31) == 0) red[i >> 5] = lsum;
    __syncthreads();
    if (i == 0) {
        float tot = red[0] + red[1] + red[2] + red[3];
        out_idx[t] = (float)idx;
        atomicAdd(&g_counts[idx], 1.0f);
        atomicAdd(&g_loss, (double)tot);
    }
}

// ------------------------------------------------------------------
// K4: new_cluster_size + its global sum
// ------------------------------------------------------------------
__global__ void k_cluster(const float* __restrict__ cs, float* __restrict__ out_cs) {
    __shared__ float red[8];
    int k = blockIdx.x * 256 + threadIdx.x;
    float v = cs[k] * DECAY_F + g_counts[k] * OMD_F;
    out_cs[k] = v;
    float sum = v;
#pragma unroll
    for (int off = 16; off; off >>= 1) sum += __shfl_xor_sync(0xFFFFFFFFu, sum, off);
    if ((threadIdx.x & 31) == 0) red[threadIdx.x >> 5] = sum;
    __syncthreads();
    if (threadIdx.x == 0) {
        float tot = 0.f;
#pragma unroll
        for (int w = 0; w < 8; w++) tot += red[w];
        atomicAdd(&g_nsum, tot);
    }
}

// ------------------------------------------------------------------
// K5: new_embed_avg, new_codebook, vq_loss scalar.
// ------------------------------------------------------------------
__global__ void k_final(const float* __restrict__ ea, const float* __restrict__ ncs_arr,
                        float* __restrict__ out_cb, float* __restrict__ out_ea,
                        float* __restrict__ out_loss) {
    const int k = blockIdx.x;
    if (k == 0 && threadIdx.x == 0) {
        out_loss[0] = 0.25f * (float)(g_loss / (double)((size_t)T_TOK * C_DIM));
    }
    float n = fmaxf(g_nsum, 1.0f);
    float ncs = ncs_arr[k];
    float sm = (ncs + EPS_F) / (n + KEPS_F) * n;

    const float4* a4 = (const float4*)(ea + (size_t)k * C_DIM);
    const float4* s4 = (const float4*)(g_embed_sum + (size_t)k * C_DIM);
    const int i = threadIdx.x;
    float4 av = a4[i];
    float4 sv = s4[i];
    float ne[4];
    ne[0] = av.x * DECAY_F + sv.x * OMD_F;
    ne[1] = av.y * DECAY_F + sv.y * OMD_F;
    ne[2] = av.z * DECAY_F + sv.z * OMD_F;
    ne[3] = av.w * DECAY_F + sv.w * OMD_F;
    size_t base = (size_t)k * C_DIM + 4 * i;
#pragma unroll
    for (int j = 0; j < 4; j++) {
        out_ea[base + j] = ne[j];
        out_cb[base + j] = ne[j] / sm;   // out offsets are 1 mod 4 -> scalar stores
    }
}

// ------------------------------------------------------------------
// launch
// ------------------------------------------------------------------
extern "C" void kernel_launch(void* const* d_in, const int* in_sizes, int n_in,
                              void* d_out, int out_size) {
    const float* Z  = (const float*)d_in[0];
    const float* E  = (const float*)d_in[1];
    const float* CS = (const float*)d_in[2];
    const float* EA = (const float*)d_in[3];

    float* out = (float*)d_out;
    float* out_zq   = out;
    float* out_idx  = out_zq + (size_t)T_TOK * C_DIM;
    float* out_loss = out_idx + T_TOK;
    float* out_cb   = out_loss + 1;
    float* out_cs   = out_cb + (size_t)K_CODE * C_DIM;
    float* out_ea   = out_cs + K_CODE;

    cudaFuncSetAttribute(k_gemm_bf16, cudaFuncAttributeMaxDynamicSharedMemorySize, SMEMB);

    k_init<<<2048, 256>>>();
    k_norms<<<(T_TOK + K_CODE) / 8, 256>>>(Z, E);
    k_split<<<(T_TOK * C_DIM) / 256, 256>>>(Z, E);
    dim3 grid(K_CODE / TILE_N, T_TOK / TILE_M);   // (32, 64)
    k_gemm_bf16<<<grid, 256, SMEMB>>>();
    k_recheck<<<T_TOK, 256>>>(Z, E);
    k_token<<<T_TOK, 128>>>(Z, E, out_zq, out_idx);
    k_cluster<<<K_CODE / 256, 256>>>(CS, out_cs);
    k_final<<<K_CODE, 128>>>(EA, out_cs, out_cb, out_ea, out_loss);
}

// round 12
// speedup vs baseline: 3.3488x; 1.1280x over previous
#include <cuda_runtime.h>
#include <cuda_bf16.h>
#include <cuda_fp16.h>
#include <cstdint>

// Problem constants
#define T_TOK 8192
#define K_CODE 8192
#define C_DIM 512
#define KSPLIT 512             // plain bf16 GEMM

// EMA / loss constants
#define DECAY_F 0.99f
#define OMD_F ((float)(1.0 - 0.99))
#define EPS_F 1e-5f
#define KEPS_F 0.08192f

#define MARGIN 0.125f          // ~89 sigma of bf16 dist error + fp16 quantization
#define CAP 2048

// -------- scratch (device globals; no allocation allowed) --------
__device__ __align__(16) unsigned long long g_keys[T_TOK];
__device__ __align__(16) unsigned g_amin[T_TOK];                        // f2ord(shifted min)
__device__ __align__(16) float g_stok[T_TOK];
__device__ __align__(16) float g_hcode[K_CODE];
__device__ __align__(16) float g_counts[K_CODE];
__device__ __align__(16) float g_embed_sum[(size_t)K_CODE * C_DIM];
__device__ __align__(16) __nv_bfloat16 g_A2h[(size_t)T_TOK * KSPLIT];   // bf16(Z)
__device__ __align__(16) __nv_bfloat16 g_B2h[(size_t)K_CODE * KSPLIT];  // bf16(E)
__device__ __align__(16) __half g_dh[(size_t)T_TOK * K_CODE];           // fp16 shifted dists
__device__ double g_loss;
__device__ float g_nsum;

// ------------------------------------------------------------------
// helpers
// ------------------------------------------------------------------
__device__ __forceinline__ uint32_t smem_u32(const void* p) {
    uint32_t a;
    asm("{ .reg .u64 t; cvta.to.shared.u64 t, %1; cvt.u32.u64 %0, t; }"
        : "=r"(a) : "l"(p));
    return a;
}
__device__ __forceinline__ unsigned f2ord(float f) {
    unsigned u = __float_as_uint(f);
    return (u & 0x80000000u) ? ~u : (u | 0x80000000u);
}
__device__ __forceinline__ float ord2f(unsigned u) {
    return (u & 0x80000000u) ? __uint_as_float(u & 0x7FFFFFFFu)
                             : __uint_as_float(~u);
}

#define LDSM_X4(r0, r1, r2, r3, addr) \
    asm volatile("ldmatrix.sync.aligned.m8n8.x4.shared.b16 {%0,%1,%2,%3}, [%4];" \
                 : "=r"(r0), "=r"(r1), "=r"(r2), "=r"(r3) : "r"(addr))

// ------------------------------------------------------------------
// K0: init scratch
// ------------------------------------------------------------------
__global__ void k_init() {
    size_t i = (size_t)blockIdx.x * blockDim.x + threadIdx.x;
    size_t stride = (size_t)gridDim.x * blockDim.x;
    float4 z4 = make_float4(0.f, 0.f, 0.f, 0.f);
    float4* es4 = (float4*)g_embed_sum;
    const size_t n4 = (size_t)K_CODE * C_DIM / 4;
    for (size_t j = i; j < n4; j += stride) es4[j] = z4;
    for (size_t j = i; j < K_CODE; j += stride) g_counts[j] = 0.f;
    for (size_t j = i; j < T_TOK; j += stride) { g_keys[j] = ~0ull; g_amin[j] = 0xFFFFFFFFu; }
    if (i == 0) { g_loss = 0.0; g_nsum = 0.f; }
}

// ------------------------------------------------------------------
// K1: fused row norms + bf16 convert (one warp per row; rows 0..T-1 = Z,
//     rows T..T+K-1 = E). Norm computed EXACTLY like the R5 kernel.
// ------------------------------------------------------------------
__global__ void k_prep(const float* __restrict__ Z, const float* __restrict__ E) {
    int warp = (int)((blockIdx.x * blockDim.x + threadIdx.x) >> 5);
    int lane = threadIdx.x & 31;
    if (warp >= T_TOK + K_CODE) return;
    const bool isZ = warp < T_TOK;
    const int row = isZ ? warp : warp - T_TOK;
    const float* p = isZ ? (Z + (size_t)row * C_DIM) : (E + (size_t)row * C_DIM);
    __nv_bfloat16* q = isZ ? (g_A2h + (size_t)row * KSPLIT) : (g_B2h + (size_t)row * KSPLIT);
    const float4* p4 = (const float4*)p;
    float s = 0.f;
#pragma unroll
    for (int i = 0; i < C_DIM / 128; i++) {
        float4 v = p4[lane + i * 32];
        s += v.x * v.x + v.y * v.y + v.z * v.z + v.w * v.w;
        __nv_bfloat162* q2 = (__nv_bfloat162*)(q + (lane + i * 32) * 4);
        q2[0] = __nv_bfloat162(__float2bfloat16(v.x), __float2bfloat16(v.y));
        q2[1] = __nv_bfloat162(__float2bfloat16(v.z), __float2bfloat16(v.w));
    }
#pragma unroll
    for (int off = 16; off; off >>= 1) s += __shfl_xor_sync(0xFFFFFFFFu, s, off);
    if (lane == 0) {
        if (isZ) g_stok[row] = s;
        else     g_hcode[row] = s;
    }
}

// ------------------------------------------------------------------
// K2: bf16 mma.sync GEMM -> fp16 SHIFTED dists (h - 2*dot) + f2ord minima.
//   CTA 128x128, 128 threads, 4 warps (2x2), warp tile 64x64.
//   2 CTAs/SM (occupancy doubled vs R10 at same per-warp shape).
// ------------------------------------------------------------------
#define TILE_M 128
#define TILE_N 128
#define BKB 32
#define RST 40
#define STAGE_BF ((TILE_M + TILE_N) * RST)      // 10240 bf16
#define STAGE_BYTES (STAGE_BF * 2)              // 20480
#define NSTAGE 4
#define SMEMB (NSTAGE * STAGE_BYTES)            // 81920
#define NIT (KSPLIT / BKB)                      // 16

__global__ __launch_bounds__(128, 2) void k_gemm_bf16() {
    extern __shared__ __align__(16) __nv_bfloat16 smb[];
    const uint32_t sm_base = smem_u32(smb);
    const int tid = threadIdx.x;
    const int wid = tid >> 5, lane = tid & 31;
    const int g = lane >> 2, t = lane & 3;
    const int wm = wid >> 1, wn = wid & 1;     // 2 x 2 warp grid
    const int bm = blockIdx.y * TILE_M;
    const int bn = blockIdx.x * TILE_N;

    float acc[4][8][4];
#pragma unroll
    for (int a = 0; a < 4; a++)
#pragma unroll
        for (int b = 0; b < 8; b++)
#pragma unroll
            for (int c = 0; c < 4; c++) acc[a][b][c] = 0.f;

    // cp.async mapping: 1024 16B-chunks per stage (256 rows x 4 segs), 8/thread
    const __nv_bfloat16* srcp[8];
    uint32_t dsto[8];
#pragma unroll
    for (int i = 0; i < 8; i++) {
        int q = tid + i * 128;
        int row = q >> 2;
        int seg = q & 3;                 // 8 bf16 per 16B segment
        srcp[i] = (row < TILE_M)
                    ? (g_A2h + (size_t)(bm + row) * KSPLIT + seg * 8)
                    : (g_B2h + (size_t)(bn + (row - TILE_M)) * KSPLIT + seg * 8);
        dsto[i] = (uint32_t)(row * RST + seg * 8) * 2u;
    }

    auto load_stage = [&](int c) {
        uint32_t buf = (uint32_t)(c % NSTAGE) * STAGE_BYTES;
#pragma unroll
        for (int i = 0; i < 8; i++) {
            asm volatile("cp.async.cg.shared.global [%0], [%1], 16;"
                         :: "r"(sm_base + buf + dsto[i]),
                            "l"(srcp[i] + (size_t)c * BKB) : "memory");
        }
        asm volatile("cp.async.commit_group;" ::: "memory");
    };

    // ldmatrix per-lane element offsets (bf16 elements within a stage)
    const int lrow = lane & 7, blk = lane >> 3;
    const uint32_t a_elem = (uint32_t)((wm * 64 + (blk & 1) * 8 + lrow) * RST + (blk >> 1) * 8);
    uint32_t b_elem[4];
#pragma unroll
    for (int nfp = 0; nfp < 4; nfp++)
        b_elem[nfp] = (uint32_t)((TILE_M + wn * 64 + nfp * 16 + (blk >> 1) * 8 + lrow) * RST
                                 + (blk & 1) * 8);

    load_stage(0);
    load_stage(1);
    load_stage(2);

    for (int c = 0; c < NIT; c++) {
        if (c + 2 < NIT)      asm volatile("cp.async.wait_group 2;" ::: "memory");
        else if (c + 1 < NIT) asm volatile("cp.async.wait_group 1;" ::: "memory");
        else                  asm volatile("cp.async.wait_group 0;" ::: "memory");
        __syncthreads();                 // all warps past compute of stage c-1
        if (c + 3 < NIT) load_stage(c + 3);

        const uint32_t sbuf = sm_base + (uint32_t)(c % NSTAGE) * STAGE_BYTES;

#pragma unroll
        for (int ks = 0; ks < 2; ks++) {
            const uint32_t k0 = ks * 16;
            uint32_t af[4][4];
#pragma unroll
            for (int mf = 0; mf < 4; mf++) {
                uint32_t addr = sbuf + (a_elem + (uint32_t)(mf * 16 * RST) + k0) * 2u;
                LDSM_X4(af[mf][0], af[mf][1], af[mf][2], af[mf][3], addr);
            }
            uint32_t bfr[8][2];
#pragma unroll
            for (int nfp = 0; nfp < 4; nfp++) {
                uint32_t addr = sbuf + (b_elem[nfp] + k0) * 2u;
                LDSM_X4(bfr[2 * nfp][0], bfr[2 * nfp][1],
                        bfr[2 * nfp + 1][0], bfr[2 * nfp + 1][1], addr);
            }
#pragma unroll
            for (int mf = 0; mf < 4; mf++)
#pragma unroll
                for (int nf = 0; nf < 8; nf++) {
                    float* d = acc[mf][nf];
                    asm volatile(
                        "mma.sync.aligned.m16n8k16.row.col.f32.bf16.bf16.f32 "
                        "{%0,%1,%2,%3}, {%4,%5,%6,%7}, {%8,%9}, {%0,%1,%2,%3};"
                        : "+f"(d[0]), "+f"(d[1]), "+f"(d[2]), "+f"(d[3])
                        : "r"(af[mf][0]), "r"(af[mf][1]), "r"(af[mf][2]), "r"(af[mf][3]),
                          "r"(bfr[nf][0]), "r"(bfr[nf][1]));
                }
        }
    }

    // ---- epilogue: store fp16 SHIFTED dists (h - 2*dot) + f2ord row minima ----
    // acc d0=D[g][2t], d1=D[g][2t+1], d2=D[g+8][2t], d3=D[g+8][2t+1]
#pragma unroll
    for (int mf = 0; mf < 4; mf++) {
        int r0 = bm + wm * 64 + mf * 16 + g;
        float m0 = 3.4e38f, m1 = 3.4e38f;
#pragma unroll
        for (int nf = 0; nf < 8; nf++) {
            int c0 = bn + wn * 64 + nf * 8 + 2 * t;
            float h0 = g_hcode[c0];
            float h1 = g_hcode[c0 + 1];
            const float* d = acc[mf][nf];
            float v00 = h0 - 2.0f * d[0], v01 = h1 - 2.0f * d[1];
            float v10 = h0 - 2.0f * d[2], v11 = h1 - 2.0f * d[3];
            *(__half2*)(g_dh + (size_t)r0 * K_CODE + c0) =
                __floats2half2_rn(v00, v01);
            *(__half2*)(g_dh + (size_t)(r0 + 8) * K_CODE + c0) =
                __floats2half2_rn(v10, v11);
            m0 = fminf(m0, fminf(v00, v01));
            m1 = fminf(m1, fminf(v10, v11));
        }
#pragma unroll
        for (int off = 1; off <= 2; off <<= 1) {
            m0 = fminf(m0, __shfl_xor_sync(0xFFFFFFFFu, m0, off));
            m1 = fminf(m1, __shfl_xor_sync(0xFFFFFFFFu, m1, off));
        }
        if (t == 0) {
            atomicMin(&g_amin[r0], f2ord(m0));
            atomicMin(&g_amin[r0 + 8], f2ord(m1));
        }
    }
}

// ------------------------------------------------------------------
// K2b: exact re-check. One block (256 thr) per token — SINGLE pass over
//   fp16 shifted dists; band = {j : v_j < min + MARGIN} (shift cancels).
//   Band members recomputed with the EXACT R5 operation order
//   (sequential-k fmaf, (s-2*acc)+h, u64 key, atomicMin)
//   -> g_keys bit-identical to the R5-passing kernel.
// ------------------------------------------------------------------
__global__ __launch_bounds__(256) void k_recheck(const float* __restrict__ Z,
                                                 const float* __restrict__ E) {
    __shared__ int s_cnt;
    __shared__ int s_list[CAP];
    const int t = blockIdx.x;
    const int tid = threadIdx.x;
    const __half2* drow2 = (const __half2*)(g_dh + (size_t)t * K_CODE);

    if (tid == 0) s_cnt = 0;
    __syncthreads();
    const float thr = ord2f(g_amin[t]) + MARGIN;

    for (int j2 = tid; j2 < K_CODE / 2; j2 += 256) {
        float2 v = __half22float2(drow2[j2]);
        if (v.x < thr) { int p = atomicAdd(&s_cnt, 1); if (p < CAP) s_list[p] = 2 * j2; }
        if (v.y < thr) { int p = atomicAdd(&s_cnt, 1); if (p < CAP) s_list[p] = 2 * j2 + 1; }
    }
    __syncthreads();

    const float s_tok = g_stok[t];
    const float* zp = Z + (size_t)t * C_DIM;
    const int n = s_cnt;
    unsigned long long best = ~0ull;

    auto proc = [&](int j) {
        const float* ep = E + (size_t)j * C_DIM;
        float a = 0.f;
#pragma unroll 8
        for (int k = 0; k < C_DIM; k++) a = fmaf(zp[k], ep[k], a);  // sequential chain
        float dist = (s_tok - 2.0f * a) + g_hcode[j];
        unsigned long long key = ((unsigned long long)f2ord(dist) << 32) | (unsigned)j;
        best = (key < best) ? key : best;
    };

    if (n <= CAP) {
        for (int i = tid; i < n; i += 256) proc(s_list[i]);
    } else {
        for (int j2 = 0; j2 < K_CODE / 2; j2 += 256) {
            int jj = 2 * (j2 + tid);
            if (j2 + tid < K_CODE / 2) {
                float2 v = __half22float2(drow2[j2 + tid]);
                if (v.x < thr) proc(jj);
                if (v.y < thr) proc(jj + 1);
            }
        }
    }
    if (best != ~0ull) atomicMin(&g_keys[t], best);
}

// ------------------------------------------------------------------
// K3: per-token: gather z_q, straight-through out, loss, counts,
//     embed_sum scatter. One block (128 threads) per token.
// ------------------------------------------------------------------
__global__ void k_token(const float* __restrict__ Z, const float* __restrict__ E,
                        float* __restrict__ out_zq, float* __restrict__ out_idx) {
    __shared__ float red[4];
    const int t = blockIdx.x;
    const int idx = (int)(g_keys[t] & 0xFFFFFFFFull);
    const float4* z4 = (const float4*)(Z + (size_t)t * C_DIM);
    const float4* e4 = (const float4*)(E + (size_t)idx * C_DIM);
    float4* o4 = (float4*)(out_zq + (size_t)t * C_DIM);
    float* es = g_embed_sum + (size_t)idx * C_DIM;

    const int i = threadIdx.x;
    float4 zv = z4[i];
    float4 ev = e4[i];
    float4 o;
    o.x = zv.x + (ev.x - zv.x);
    o.y = zv.y + (ev.y - zv.y);
    o.z = zv.z + (ev.z - zv.z);
    o.w = zv.w + (ev.w - zv.w);
    o4[i] = o;
    float dx = zv.x - ev.x, dy = zv.y - ev.y, dz = zv.z - ev.z, dw = zv.w - ev.w;
    float lsum = dx * dx + dy * dy + dz * dz + dw * dw;

    atomicAdd(&es[4 * i + 0], zv.x);
    atomicAdd(&es[4 * i + 1], zv.y);
    atomicAdd(&es[4 * i + 2], zv.z);
    atomicAdd(&es[4 * i + 3], zv.w);

#pragma unroll
    for (int off = 16; off; off >>= 1) lsum += __shfl_xor_sync(0xFFFFFFFFu, lsum, off);
    if ((i & 31) == 0) red[i >> 5] = lsum;
    __syncthreads();
    if (i == 0) {
        float tot = red[0] + red[1] + red[2] + red[3];
        out_idx[t] = (float)idx;
        atomicAdd(&g_counts[idx], 1.0f);
        atomicAdd(&g_loss, (double)tot);
    }
}

// ------------------------------------------------------------------
// K4: new_cluster_size + its global sum
// ------------------------------------------------------------------
__global__ void k_cluster(const float* __restrict__ cs, float* __restrict__ out_cs) {
    __shared__ float red[8];
    int k = blockIdx.x * 256 + threadIdx.x;
    float v = cs[k] * DECAY_F + g_counts[k] * OMD_F;
    out_cs[k] = v;
    float sum = v;
#pragma unroll
    for (int off = 16; off; off >>= 1) sum += __shfl_xor_sync(0xFFFFFFFFu, sum, off);
    if ((threadIdx.x & 31) == 0) red[threadIdx.x >> 5] = sum;
    __syncthreads();
    if (threadIdx.x == 0) {
        float tot = 0.f;
#pragma unroll
        for (int w = 0; w < 8; w++) tot += red[w];
        atomicAdd(&g_nsum, tot);
    }
}

// ------------------------------------------------------------------
// K5: new_embed_avg, new_codebook, vq_loss scalar.
// ------------------------------------------------------------------
__global__ void k_final(const float* __restrict__ ea, const float* __restrict__ ncs_arr,
                        float* __restrict__ out_cb, float* __restrict__ out_ea,
                        float* __restrict__ out_loss) {
    const int k = blockIdx.x;
    if (k == 0 && threadIdx.x == 0) {
        out_loss[0] = 0.25f * (float)(g_loss / (double)((size_t)T_TOK * C_DIM));
    }
    float n = fmaxf(g_nsum, 1.0f);
    float ncs = ncs_arr[k];
    float sm = (ncs + EPS_F) / (n + KEPS_F) * n;

    const float4* a4 = (const float4*)(ea + (size_t)k * C_DIM);
    const float4* s4 = (const float4*)(g_embed_sum + (size_t)k * C_DIM);
    const int i = threadIdx.x;
    float4 av = a4[i];
    float4 sv = s4[i];
    float ne[4];
    ne[0] = av.x * DECAY_F + sv.x * OMD_F;
    ne[1] = av.y * DECAY_F + sv.y * OMD_F;
    ne[2] = av.z * DECAY_F + sv.z * OMD_F;
    ne[3] = av.w * DECAY_F + sv.w * OMD_F;
    size_t base = (size_t)k * C_DIM + 4 * i;
#pragma unroll
    for (int j = 0; j < 4; j++) {
        out_ea[base + j] = ne[j];
        out_cb[base + j] = ne[j] / sm;   // out offsets are 1 mod 4 -> scalar stores
    }
}

// ------------------------------------------------------------------
// launch
// ------------------------------------------------------------------
extern "C" void kernel_launch(void* const* d_in, const int* in_sizes, int n_in,
                              void* d_out, int out_size) {
    const float* Z  = (const float*)d_in[0];
    const float* E  = (const float*)d_in[1];
    const float* CS = (const float*)d_in[2];
    const float* EA = (const float*)d_in[3];

    float* out = (float*)d_out;
    float* out_zq   = out;
    float* out_idx  = out_zq + (size_t)T_TOK * C_DIM;
    float* out_loss = out_idx + T_TOK;
    float* out_cb   = out_loss + 1;
    float* out_cs   = out_cb + (size_t)K_CODE * C_DIM;
    float* out_ea   = out_cs + K_CODE;

    cudaFuncSetAttribute(k_gemm_bf16, cudaFuncAttributeMaxDynamicSharedMemorySize, SMEMB);

    k_init<<<2048, 256>>>();
    k_prep<<<(T_TOK + K_CODE) / 8, 256>>>(Z, E);
    dim3 grid(K_CODE / TILE_N, T_TOK / TILE_M);   // (64, 64)
    k_gemm_bf16<<<grid, 128, SMEMB>>>();
    k_recheck<<<T_TOK, 256>>>(Z, E);
    k_token<<<T_TOK, 128>>>(Z, E, out_zq, out_idx);
    k_cluster<<<K_CODE / 256, 256>>>(CS, out_cs);
    k_final<<<K_CODE, 128>>>(EA, out_cs, out_cb, out_ea, out_loss);
}